// round 4
// baseline (speedup 1.0000x reference)
#include <cuda_runtime.h>
#include <math.h>

#define N_NODES 100000
#define N_EDGES 500000
#define HIDDEN  32
#define HEADS   4
#define PROJ    128
#define LN_EPS  1e-5f

// Folded parameters:
//   P[h][j][d], j=0..2: coefficient of rel_j in (Wv_h @ Wout_h); j=3: bv_h @ Wout_h
//   M[h][3x3]: Wq_h Wk_h^T / sqrt(32)   (quadratic-form score matrix)
//   a[h][3], s[h]: bias-linear and bias-bias score terms (zero here, kept for generality)
struct __align__(16) Params {
    float P[HEADS][4][HIDDEN];   // 512 floats
    float M[HEADS][9];           // 36
    float a[HEADS][3];           // 12
    float s[HEADS];              // 4
};

__device__ Params g_params;
__device__ __align__(16) float g_accum[N_NODES * HIDDEN];
__device__ int g_counts[N_NODES];

__device__ __forceinline__ void red_add_v4(float* addr, float x, float y, float z, float w) {
    asm volatile("red.global.add.v4.f32 [%0], {%1, %2, %3, %4};"
                 :: "l"(addr), "f"(x), "f"(y), "f"(z), "f"(w) : "memory");
}

// ---------------------------------------------------------------------------
// Kernel 0: zero the scratch accumulators (graph is replayed; must re-zero)
// ---------------------------------------------------------------------------
__global__ void zero_kernel() {
    int i = blockIdx.x * blockDim.x + threadIdx.x;
    if (i < N_NODES * HIDDEN) g_accum[i] = 0.0f;
    if (i < N_NODES)          g_counts[i] = 0;
}

// ---------------------------------------------------------------------------
// Kernel 1: fold weights into the tiny Params struct. 1 block, 128 threads.
// ---------------------------------------------------------------------------
__global__ void precompute_kernel(const float* __restrict__ Wq, const float* __restrict__ bq,
                                  const float* __restrict__ Wk, const float* __restrict__ bk,
                                  const float* __restrict__ Wv, const float* __restrict__ bv,
                                  const float* __restrict__ Wout) {
    const int t = threadIdx.x;          // 0..127
    const int h = t >> 5;               // head
    const int d = t & 31;               // output channel within HIDDEN

    // P[h][*][d] = sum_m Wv[*][h*32+m] * Wout[h*32+m][d]
    float p0 = 0.f, p1 = 0.f, p2 = 0.f, p3 = 0.f;
    #pragma unroll 4
    for (int m = 0; m < 32; m++) {
        const int pm = h * 32 + m;
        const float wo = Wout[pm * HIDDEN + d];
        p0 = fmaf(Wv[0 * PROJ + pm], wo, p0);
        p1 = fmaf(Wv[1 * PROJ + pm], wo, p1);
        p2 = fmaf(Wv[2 * PROJ + pm], wo, p2);
        p3 = fmaf(bv[pm], wo, p3);
    }
    g_params.P[h][0][d] = p0;
    g_params.P[h][1][d] = p1;
    g_params.P[h][2][d] = p2;
    g_params.P[h][3][d] = p3;

    // score-form terms: M, a, s (4 threads, one per head)
    if (t < HEADS) {
        const int hh = t;
        const float invs = 1.0f / sqrtf((float)HIDDEN);
        #pragma unroll
        for (int i = 0; i < 3; i++) {
            #pragma unroll
            for (int j = 0; j < 3; j++) {
                float acc = 0.f;
                for (int m = 0; m < 32; m++)
                    acc = fmaf(Wq[i * PROJ + hh * 32 + m], Wk[j * PROJ + hh * 32 + m], acc);
                g_params.M[hh][i * 3 + j] = acc * invs;
            }
            float av = 0.f;
            for (int m = 0; m < 32; m++) {
                av = fmaf(Wq[i * PROJ + hh * 32 + m], bk[hh * 32 + m], av);
                av = fmaf(Wk[i * PROJ + hh * 32 + m], bq[hh * 32 + m], av);
            }
            g_params.a[hh][i] = av * invs;
        }
        float sv = 0.f;
        for (int m = 0; m < 32; m++)
            sv = fmaf(bq[hh * 32 + m], bk[hh * 32 + m], sv);
        g_params.s[hh] = sv * invs;
    }
}

// ---------------------------------------------------------------------------
// Kernel 2: per-edge score + softmax + folded output, scattered with RED.128
// NOTE: edge_index arrives as int32 (JAX x64-disabled demotes int64 -> int32).
// ---------------------------------------------------------------------------
__global__ void __launch_bounds__(256) edge_kernel(const float* __restrict__ pos,
                                                   const int* __restrict__ ei) {
    __shared__ Params sp;
    {
        const float* src = (const float*)&g_params;
        float* dst = (float*)&sp;
        for (int i = threadIdx.x; i < (int)(sizeof(Params) / 4); i += blockDim.x)
            dst[i] = src[i];
    }
    __syncthreads();

    const int e = blockIdx.x * blockDim.x + threadIdx.x;
    if (e >= N_EDGES) return;

    const int r = ei[e];
    const int c = ei[N_EDGES + e];

    const float r0 = __ldg(&pos[r * 3 + 0]) - __ldg(&pos[c * 3 + 0]);
    const float r1 = __ldg(&pos[r * 3 + 1]) - __ldg(&pos[c * 3 + 1]);
    const float r2 = __ldg(&pos[r * 3 + 2]) - __ldg(&pos[c * 3 + 2]);

    // scores: rel^T M_h rel + a_h . rel + s_h
    float sc[HEADS];
    #pragma unroll
    for (int h = 0; h < HEADS; h++) {
        const float* M = sp.M[h];
        const float t0 = fmaf(M[0], r0, fmaf(M[1], r1, M[2] * r2));
        const float t1 = fmaf(M[3], r0, fmaf(M[4], r1, M[5] * r2));
        const float t2 = fmaf(M[6], r0, fmaf(M[7], r1, M[8] * r2));
        float s = fmaf(r0, t0, fmaf(r1, t1, r2 * t2));
        s = fmaf(sp.a[h][0], r0, s);
        s = fmaf(sp.a[h][1], r1, s);
        s = fmaf(sp.a[h][2], r2, s);
        sc[h] = s + sp.s[h];
    }

    // softmax over 4 heads
    float mx = fmaxf(fmaxf(sc[0], sc[1]), fmaxf(sc[2], sc[3]));
    float w[HEADS], sum = 0.f;
    #pragma unroll
    for (int h = 0; h < HEADS; h++) { w[h] = __expf(sc[h] - mx); sum += w[h]; }
    const float inv = 1.0f / sum;

    // per-edge blend coefficients: eC[h][j] multiplies P[h][j][d]
    float eC[HEADS][4];
    #pragma unroll
    for (int h = 0; h < HEADS; h++) {
        const float wh = w[h] * inv;
        eC[h][0] = wh * r0;
        eC[h][1] = wh * r1;
        eC[h][2] = wh * r2;
        eC[h][3] = wh;
    }

    float* base = &g_accum[c * HIDDEN];
    #pragma unroll
    for (int g = 0; g < HIDDEN; g += 4) {
        float ax = 0.f, ay = 0.f, az = 0.f, aw = 0.f;
        #pragma unroll
        for (int h = 0; h < HEADS; h++) {
            #pragma unroll
            for (int j = 0; j < 4; j++) {
                const float4 p = *(const float4*)&sp.P[h][j][g];
                const float cc = eC[h][j];
                ax = fmaf(cc, p.x, ax);
                ay = fmaf(cc, p.y, ay);
                az = fmaf(cc, p.z, az);
                aw = fmaf(cc, p.w, aw);
            }
        }
        red_add_v4(base + g, ax, ay, az, aw);
    }
    atomicAdd(&g_counts[c], 1);
}

// ---------------------------------------------------------------------------
// Kernel 3: per-node mean + bias + LayerNorm + SiLU. One warp per node.
// ---------------------------------------------------------------------------
__global__ void __launch_bounds__(256) node_kernel(const float* __restrict__ bout,
                                                   const float* __restrict__ gamma,
                                                   const float* __restrict__ beta,
                                                   float* __restrict__ out) {
    const int gtid = blockIdx.x * blockDim.x + threadIdx.x;
    const int node = gtid >> 5;
    const int lane = gtid & 31;
    if (node >= N_NODES) return;

    const float cnt = fmaxf((float)g_counts[node], 1.0f);
    float x = g_accum[node * HIDDEN + lane] / cnt + __ldg(&bout[lane]);

    // mean
    float mu = x;
    #pragma unroll
    for (int o = 16; o > 0; o >>= 1) mu += __shfl_xor_sync(0xFFFFFFFFu, mu, o);
    mu *= (1.0f / HIDDEN);

    const float dv = x - mu;
    float var = dv * dv;
    #pragma unroll
    for (int o = 16; o > 0; o >>= 1) var += __shfl_xor_sync(0xFFFFFFFFu, var, o);
    var *= (1.0f / HIDDEN);

    float y = dv * rsqrtf(var + LN_EPS) * __ldg(&gamma[lane]) + __ldg(&beta[lane]);
    // SiLU
    out[node * HIDDEN + lane] = y / (1.0f + __expf(-y));
}

// ---------------------------------------------------------------------------
extern "C" void kernel_launch(void* const* d_in, const int* in_sizes, int n_in,
                              void* d_out, int out_size) {
    const float* positions = (const float*)d_in[0];
    const int*   edge_idx  = (const int*)d_in[1];    // int32: JAX demotes int64
    const float* Wq   = (const float*)d_in[2];
    const float* bq   = (const float*)d_in[3];
    const float* Wk   = (const float*)d_in[4];
    const float* bk   = (const float*)d_in[5];
    const float* Wv   = (const float*)d_in[6];
    const float* bv   = (const float*)d_in[7];
    const float* Wout = (const float*)d_in[8];
    const float* bout = (const float*)d_in[9];
    const float* gamma = (const float*)d_in[10];
    const float* beta  = (const float*)d_in[11];
    float* out = (float*)d_out;

    zero_kernel<<<(N_NODES * HIDDEN + 255) / 256, 256>>>();
    precompute_kernel<<<1, 128>>>(Wq, bq, Wk, bk, Wv, bv, Wout);
    edge_kernel<<<(N_EDGES + 255) / 256, 256>>>(positions, edge_idx);
    node_kernel<<<(N_NODES * 32 + 255) / 256, 256>>>(bout, gamma, beta, out);
}

// round 7
// speedup vs baseline: 1.5991x; 1.5991x over previous
#include <cuda_runtime.h>
#include <math.h>

#define N_NODES 100000
#define N_EDGES 500000
#define HIDDEN  32
#define HEADS   4
#define PROJ    128
#define LN_EPS  1e-5f

// Folded parameters.
//   P[i][d], i = 4h+j: coefficient mapping z[i] -> output channel d,
//       j=0..2: rel_j coefficient of (Wv_h @ Wout_h); j=3: bv_h @ Wout_h
//   M[h][3x3] = Wq_h Wk_h^T / sqrt(32); a[h], s[h]: bias score terms.
// M, a, s are contiguous (52 floats) for one smem copy.
struct __align__(16) Params {
    float P[16][HIDDEN];   // 512 floats
    float M[HEADS][9];     // 36
    float a[HEADS][3];     // 12
    float s[HEADS];        // 4  -> M..s contiguous: 52 floats
};

__device__ Params g_params;
// per-node reduced accumulator: z[n][i], i = 4h+j  (attn_h * {r0,r1,r2,1})
__device__ __align__(16) float g_z[N_NODES * 16];

__device__ __forceinline__ void red_add_v4(float* addr, float x, float y, float z, float w) {
    asm volatile("red.global.add.v4.f32 [%0], {%1, %2, %3, %4};"
                 :: "l"(addr), "f"(x), "f"(y), "f"(z), "f"(w) : "memory");
}

// ---------------------------------------------------------------------------
// Kernel 0: zero the z accumulators (graph is replayed; must re-zero)
// ---------------------------------------------------------------------------
__global__ void zero_kernel() {
    int i = blockIdx.x * blockDim.x + threadIdx.x;
    if (i < N_NODES * 4) ((float4*)g_z)[i] = make_float4(0.f, 0.f, 0.f, 0.f);
}

// ---------------------------------------------------------------------------
// Kernel 1: fold weights. 1 block, 128 threads.
// ---------------------------------------------------------------------------
__global__ void precompute_kernel(const float* __restrict__ Wq, const float* __restrict__ bq,
                                  const float* __restrict__ Wk, const float* __restrict__ bk,
                                  const float* __restrict__ Wv, const float* __restrict__ bv,
                                  const float* __restrict__ Wout) {
    const int t = threadIdx.x;          // 0..127
    const int h = t >> 5;               // head
    const int d = t & 31;               // output channel

    float p0 = 0.f, p1 = 0.f, p2 = 0.f, p3 = 0.f;
    #pragma unroll 4
    for (int m = 0; m < 32; m++) {
        const int pm = h * 32 + m;
        const float wo = Wout[pm * HIDDEN + d];
        p0 = fmaf(Wv[0 * PROJ + pm], wo, p0);
        p1 = fmaf(Wv[1 * PROJ + pm], wo, p1);
        p2 = fmaf(Wv[2 * PROJ + pm], wo, p2);
        p3 = fmaf(bv[pm], wo, p3);
    }
    g_params.P[h * 4 + 0][d] = p0;
    g_params.P[h * 4 + 1][d] = p1;
    g_params.P[h * 4 + 2][d] = p2;
    g_params.P[h * 4 + 3][d] = p3;

    if (t < HEADS) {
        const int hh = t;
        const float invs = 1.0f / sqrtf((float)HIDDEN);
        #pragma unroll
        for (int i = 0; i < 3; i++) {
            #pragma unroll
            for (int j = 0; j < 3; j++) {
                float acc = 0.f;
                for (int m = 0; m < 32; m++)
                    acc = fmaf(Wq[i * PROJ + hh * 32 + m], Wk[j * PROJ + hh * 32 + m], acc);
                g_params.M[hh][i * 3 + j] = acc * invs;
            }
            float av = 0.f;
            for (int m = 0; m < 32; m++) {
                av = fmaf(Wq[i * PROJ + hh * 32 + m], bk[hh * 32 + m], av);
                av = fmaf(Wk[i * PROJ + hh * 32 + m], bq[hh * 32 + m], av);
            }
            g_params.a[hh][i] = av * invs;
        }
        float sv = 0.f;
        for (int m = 0; m < 32; m++)
            sv = fmaf(bq[hh * 32 + m], bk[hh * 32 + m], sv);
        g_params.s[hh] = sv * invs;
    }
}

// ---------------------------------------------------------------------------
// Kernel 2: per-edge score + softmax; scatter only z = attn (x) (rel,1).
// 4 RED.128 per edge; no count atomic (sum_h attn_h == 1 encodes the count).
// edge_index is int32 (JAX x64-disabled demotes int64).
// ---------------------------------------------------------------------------
__global__ void __launch_bounds__(256) edge_kernel(const float* __restrict__ pos,
                                                   const int* __restrict__ ei) {
    __shared__ float sMas[52];   // M(36), a(12), s(4) contiguous
    {
        const float* src = &g_params.M[0][0];
        if (threadIdx.x < 52) sMas[threadIdx.x] = src[threadIdx.x];
    }
    __syncthreads();
    const float* sM = sMas;          // [h*9 + ..]
    const float* sA = sMas + 36;     // [h*3 + ..]
    const float* sS = sMas + 48;     // [h]

    const int e = blockIdx.x * blockDim.x + threadIdx.x;
    if (e >= N_EDGES) return;

    const int r = ei[e];
    const int c = ei[N_EDGES + e];

    const float r0 = __ldg(&pos[r * 3 + 0]) - __ldg(&pos[c * 3 + 0]);
    const float r1 = __ldg(&pos[r * 3 + 1]) - __ldg(&pos[c * 3 + 1]);
    const float r2 = __ldg(&pos[r * 3 + 2]) - __ldg(&pos[c * 3 + 2]);

    float sc[HEADS];
    #pragma unroll
    for (int h = 0; h < HEADS; h++) {
        const float* M = sM + h * 9;
        const float t0 = fmaf(M[0], r0, fmaf(M[1], r1, M[2] * r2));
        const float t1 = fmaf(M[3], r0, fmaf(M[4], r1, M[5] * r2));
        const float t2 = fmaf(M[6], r0, fmaf(M[7], r1, M[8] * r2));
        float s = fmaf(r0, t0, fmaf(r1, t1, r2 * t2));
        s = fmaf(sA[h * 3 + 0], r0, s);
        s = fmaf(sA[h * 3 + 1], r1, s);
        s = fmaf(sA[h * 3 + 2], r2, s);
        sc[h] = s + sS[h];
    }

    const float mx = fmaxf(fmaxf(sc[0], sc[1]), fmaxf(sc[2], sc[3]));
    float w[HEADS], sum = 0.f;
    #pragma unroll
    for (int h = 0; h < HEADS; h++) { w[h] = __expf(sc[h] - mx); sum += w[h]; }
    const float inv = 1.0f / sum;

    float* base = &g_z[(size_t)c * 16];
    #pragma unroll
    for (int h = 0; h < HEADS; h++) {
        const float wh = w[h] * inv;
        red_add_v4(base + 4 * h, wh * r0, wh * r1, wh * r2, wh);
    }
}

// ---------------------------------------------------------------------------
// Kernel 3: one THREAD per node. z (16) -> P^T z (32), /count, +bout, LN, SiLU.
// All reductions in registers; no shuffles.
// ---------------------------------------------------------------------------
__global__ void __launch_bounds__(256) node_kernel(const float* __restrict__ bout,
                                                   const float* __restrict__ gamma,
                                                   const float* __restrict__ beta,
                                                   float* __restrict__ out) {
    __shared__ float4 Ps[16][8];          // P[i][d] as float4 groups
    __shared__ float sb[32], sg[32], sbt[32];
    {
        const int t = threadIdx.x;
        if (t < 128) Ps[t >> 3][t & 7] = *(const float4*)&g_params.P[t >> 3][(t & 7) * 4];
        if (t < 32) { sb[t] = bout[t]; sg[t] = gamma[t]; sbt[t] = beta[t]; }
    }
    __syncthreads();

    const int n = blockIdx.x * blockDim.x + threadIdx.x;
    if (n >= N_NODES) return;

    const float4* zp = (const float4*)&g_z[(size_t)n * 16];
    const float4 z0 = zp[0], z1 = zp[1], z2 = zp[2], z3 = zp[3];
    const float z[16] = { z0.x, z0.y, z0.z, z0.w,  z1.x, z1.y, z1.z, z1.w,
                          z2.x, z2.y, z2.z, z2.w,  z3.x, z3.y, z3.z, z3.w };

    // count = sum over edges of sum_h attn_h (== 1 per edge)
    const float cnt = fmaxf(rintf(z0.w + z1.w + z2.w + z3.w), 1.0f);
    const float icnt = 1.0f / cnt;

    float4 u[8];
    #pragma unroll
    for (int q = 0; q < 8; q++) u[q] = make_float4(0.f, 0.f, 0.f, 0.f);
    #pragma unroll
    for (int i = 0; i < 16; i++) {
        const float zi = z[i];
        #pragma unroll
        for (int q = 0; q < 8; q++) {
            const float4 p = Ps[i][q];
            u[q].x = fmaf(zi, p.x, u[q].x);
            u[q].y = fmaf(zi, p.y, u[q].y);
            u[q].z = fmaf(zi, p.z, u[q].z);
            u[q].w = fmaf(zi, p.w, u[q].w);
        }
    }

    // x = u/cnt + bout; LayerNorm stats over the 32 registers
    float x[32];
    float mu = 0.f;
    #pragma unroll
    for (int q = 0; q < 8; q++) {
        x[4*q+0] = fmaf(u[q].x, icnt, sb[4*q+0]);
        x[4*q+1] = fmaf(u[q].y, icnt, sb[4*q+1]);
        x[4*q+2] = fmaf(u[q].z, icnt, sb[4*q+2]);
        x[4*q+3] = fmaf(u[q].w, icnt, sb[4*q+3]);
        mu += x[4*q+0] + x[4*q+1] + x[4*q+2] + x[4*q+3];
    }
    mu *= (1.0f / HIDDEN);

    float var = 0.f;
    #pragma unroll
    for (int d = 0; d < 32; d++) { const float dv = x[d] - mu; var += dv * dv; }
    var *= (1.0f / HIDDEN);
    const float rstd = rsqrtf(var + LN_EPS);

    float4* op = (float4*)&out[(size_t)n * 32];
    #pragma unroll
    for (int q = 0; q < 8; q++) {
        float4 o;
        float y;
        y = (x[4*q+0] - mu) * rstd * sg[4*q+0] + sbt[4*q+0]; o.x = y / (1.0f + __expf(-y));
        y = (x[4*q+1] - mu) * rstd * sg[4*q+1] + sbt[4*q+1]; o.y = y / (1.0f + __expf(-y));
        y = (x[4*q+2] - mu) * rstd * sg[4*q+2] + sbt[4*q+2]; o.z = y / (1.0f + __expf(-y));
        y = (x[4*q+3] - mu) * rstd * sg[4*q+3] + sbt[4*q+3]; o.w = y / (1.0f + __expf(-y));
        op[q] = o;
    }
}

// ---------------------------------------------------------------------------
extern "C" void kernel_launch(void* const* d_in, const int* in_sizes, int n_in,
                              void* d_out, int out_size) {
    const float* positions = (const float*)d_in[0];
    const int*   edge_idx  = (const int*)d_in[1];    // int32
    const float* Wq   = (const float*)d_in[2];
    const float* bq   = (const float*)d_in[3];
    const float* Wk   = (const float*)d_in[4];
    const float* bk   = (const float*)d_in[5];
    const float* Wv   = (const float*)d_in[6];
    const float* bv   = (const float*)d_in[7];
    const float* Wout = (const float*)d_in[8];
    const float* bout = (const float*)d_in[9];
    const float* gamma = (const float*)d_in[10];
    const float* beta  = (const float*)d_in[11];
    float* out = (float*)d_out;

    zero_kernel<<<(N_NODES * 4 + 255) / 256, 256>>>();
    precompute_kernel<<<1, 128>>>(Wq, bq, Wk, bk, Wv, bv, Wout);
    edge_kernel<<<(N_EDGES + 255) / 256, 256>>>(positions, edge_idx);
    node_kernel<<<(N_NODES + 255) / 256, 256>>>(bout, gamma, beta, out);
}

// round 8
// speedup vs baseline: 1.6998x; 1.0630x over previous
#include <cuda_runtime.h>
#include <math.h>

#define N_NODES 100000
#define N_EDGES 500000
#define HIDDEN  32
#define HEADS   4
#define PROJ    128
#define LN_EPS  1e-5f

// Folded parameters.
//   P[i][d], i = 4h+j: coefficient mapping z[i] -> output channel d,
//       j=0..2: rel_j coefficient of (Wv_h @ Wout_h); j=3: bv_h @ Wout_h
//   M[h][3x3] = Wq_h Wk_h^T / sqrt(32); a[h], s[h]: bias score terms.
struct __align__(16) Params {
    float P[16][HIDDEN];   // 512 floats
    float M[HEADS][9];     // 36
    float a[HEADS][3];     // 12
    float s[HEADS];        // 4  -> M..s contiguous: 52 floats
};

__device__ Params g_params;
// per-node reduced accumulator: z[n][i], i = 4h+j  (attn_h * {r0,r1,r2,1})
__device__ __align__(16) float g_z[N_NODES * 16];

__device__ __forceinline__ void red_add_v4(float* addr, float x, float y, float z, float w) {
    asm volatile("red.global.add.v4.f32 [%0], {%1, %2, %3, %4};"
                 :: "l"(addr), "f"(x), "f"(y), "f"(z), "f"(w) : "memory");
}

// ---------------------------------------------------------------------------
// Kernel 0: block 0 folds weights; blocks 1..N zero the z accumulators.
// ---------------------------------------------------------------------------
__global__ void init_kernel(const float* __restrict__ Wq, const float* __restrict__ bq,
                            const float* __restrict__ Wk, const float* __restrict__ bk,
                            const float* __restrict__ Wv, const float* __restrict__ bv,
                            const float* __restrict__ Wout) {
    if (blockIdx.x != 0) {
        const int i = (blockIdx.x - 1) * blockDim.x + threadIdx.x;
        if (i < N_NODES * 4) ((float4*)g_z)[i] = make_float4(0.f, 0.f, 0.f, 0.f);
        return;
    }

    const int t = threadIdx.x;
    if (t >= 128) return;
    const int h = t >> 5;               // head
    const int d = t & 31;               // output channel

    float p0 = 0.f, p1 = 0.f, p2 = 0.f, p3 = 0.f;
    #pragma unroll 4
    for (int m = 0; m < 32; m++) {
        const int pm = h * 32 + m;
        const float wo = Wout[pm * HIDDEN + d];
        p0 = fmaf(Wv[0 * PROJ + pm], wo, p0);
        p1 = fmaf(Wv[1 * PROJ + pm], wo, p1);
        p2 = fmaf(Wv[2 * PROJ + pm], wo, p2);
        p3 = fmaf(bv[pm], wo, p3);
    }
    g_params.P[h * 4 + 0][d] = p0;
    g_params.P[h * 4 + 1][d] = p1;
    g_params.P[h * 4 + 2][d] = p2;
    g_params.P[h * 4 + 3][d] = p3;

    if (t < HEADS) {
        const int hh = t;
        const float invs = 1.0f / sqrtf((float)HIDDEN);
        #pragma unroll
        for (int i = 0; i < 3; i++) {
            #pragma unroll
            for (int j = 0; j < 3; j++) {
                float acc = 0.f;
                for (int m = 0; m < 32; m++)
                    acc = fmaf(Wq[i * PROJ + hh * 32 + m], Wk[j * PROJ + hh * 32 + m], acc);
                g_params.M[hh][i * 3 + j] = acc * invs;
            }
            float av = 0.f;
            for (int m = 0; m < 32; m++) {
                av = fmaf(Wq[i * PROJ + hh * 32 + m], bk[hh * 32 + m], av);
                av = fmaf(Wk[i * PROJ + hh * 32 + m], bq[hh * 32 + m], av);
            }
            g_params.a[hh][i] = av * invs;
        }
        float sv = 0.f;
        for (int m = 0; m < 32; m++)
            sv = fmaf(bq[hh * 32 + m], bk[hh * 32 + m], sv);
        g_params.s[hh] = sv * invs;
    }
}

// ---------------------------------------------------------------------------
// Kernel 1: per-edge score + softmax; scatter z = attn (x) (rel,1).
// 4 RED.128 per edge; no count atomic (sum_h attn_h == 1 encodes the count).
// edge_index is int32 (JAX x64-disabled demotes int64).
// ---------------------------------------------------------------------------
__global__ void __launch_bounds__(256) edge_kernel(const float* __restrict__ pos,
                                                   const int* __restrict__ ei) {
    __shared__ float sMas[52];   // M(36), a(12), s(4) contiguous
    {
        const float* src = &g_params.M[0][0];
        if (threadIdx.x < 52) sMas[threadIdx.x] = src[threadIdx.x];
    }
    __syncthreads();
    const float* sM = sMas;          // [h*9 + ..]
    const float* sA = sMas + 36;     // [h*3 + ..]
    const float* sS = sMas + 48;     // [h]

    const int e = blockIdx.x * blockDim.x + threadIdx.x;
    if (e >= N_EDGES) return;

    const int r = ei[e];
    const int c = ei[N_EDGES + e];

    const float r0 = __ldg(&pos[r * 3 + 0]) - __ldg(&pos[c * 3 + 0]);
    const float r1 = __ldg(&pos[r * 3 + 1]) - __ldg(&pos[c * 3 + 1]);
    const float r2 = __ldg(&pos[r * 3 + 2]) - __ldg(&pos[c * 3 + 2]);

    float sc[HEADS];
    #pragma unroll
    for (int h = 0; h < HEADS; h++) {
        const float* M = sM + h * 9;
        const float t0 = fmaf(M[0], r0, fmaf(M[1], r1, M[2] * r2));
        const float t1 = fmaf(M[3], r0, fmaf(M[4], r1, M[5] * r2));
        const float t2 = fmaf(M[6], r0, fmaf(M[7], r1, M[8] * r2));
        float s = fmaf(r0, t0, fmaf(r1, t1, r2 * t2));
        s = fmaf(sA[h * 3 + 0], r0, s);
        s = fmaf(sA[h * 3 + 1], r1, s);
        s = fmaf(sA[h * 3 + 2], r2, s);
        sc[h] = s + sS[h];
    }

    const float mx = fmaxf(fmaxf(sc[0], sc[1]), fmaxf(sc[2], sc[3]));
    float w[HEADS], sum = 0.f;
    #pragma unroll
    for (int h = 0; h < HEADS; h++) { w[h] = __expf(sc[h] - mx); sum += w[h]; }
    const float inv = 1.0f / sum;

    float* base = &g_z[(size_t)c * 16];
    #pragma unroll
    for (int h = 0; h < HEADS; h++) {
        const float wh = w[h] * inv;
        red_add_v4(base + 4 * h, wh * r0, wh * r1, wh * r2, wh);
    }
}

// ---------------------------------------------------------------------------
// Kernel 2: FOUR threads per node. Each thread of a quad computes 8 output
// channels; z is loaded by every thread (L1 broadcast of the same 64B line);
// LayerNorm stats via 4 intra-quad shuffles. 400k threads total.
// ---------------------------------------------------------------------------
__global__ void __launch_bounds__(256) node_kernel(const float* __restrict__ bout,
                                                   const float* __restrict__ gamma,
                                                   const float* __restrict__ beta,
                                                   float* __restrict__ out) {
    __shared__ float4 Ps[16][8];          // P[i][d] as float4 groups
    __shared__ float sb[32], sg[32], sbt[32];
    {
        const int t = threadIdx.x;
        if (t < 128) Ps[t >> 3][t & 7] = *(const float4*)&g_params.P[t >> 3][(t & 7) * 4];
        if (t < 32) { sb[t] = bout[t]; sg[t] = gamma[t]; sbt[t] = beta[t]; }
    }
    __syncthreads();

    const int gt = blockIdx.x * blockDim.x + threadIdx.x;
    const int n = gt >> 2;          // node
    const int q = gt & 3;           // quad lane: channels [8q, 8q+8)
    if (n >= N_NODES) return;       // warp-uniform (400k = 12500 whole warps)

    const float4* zp = (const float4*)&g_z[(size_t)n * 16];
    const float4 z0 = zp[0], z1 = zp[1], z2 = zp[2], z3 = zp[3];
    const float z[16] = { z0.x, z0.y, z0.z, z0.w,  z1.x, z1.y, z1.z, z1.w,
                          z2.x, z2.y, z2.z, z2.w,  z3.x, z3.y, z3.z, z3.w };

    // count = sum over edges of sum_h attn_h (== 1 per edge)
    const float cnt = fmaxf(rintf(z0.w + z1.w + z2.w + z3.w), 1.0f);
    const float icnt = 1.0f / cnt;

    // u = P^T z for my 8 channels (two float4 groups: 2q, 2q+1)
    float4 u0 = make_float4(0.f, 0.f, 0.f, 0.f);
    float4 u1 = make_float4(0.f, 0.f, 0.f, 0.f);
    #pragma unroll
    for (int i = 0; i < 16; i++) {
        const float zi = z[i];
        const float4 pa = Ps[i][2 * q];
        const float4 pb = Ps[i][2 * q + 1];
        u0.x = fmaf(zi, pa.x, u0.x); u0.y = fmaf(zi, pa.y, u0.y);
        u0.z = fmaf(zi, pa.z, u0.z); u0.w = fmaf(zi, pa.w, u0.w);
        u1.x = fmaf(zi, pb.x, u1.x); u1.y = fmaf(zi, pb.y, u1.y);
        u1.z = fmaf(zi, pb.z, u1.z); u1.w = fmaf(zi, pb.w, u1.w);
    }

    // x = u/cnt + bout for my 8 channels
    const int cbase = 8 * q;
    float x[8];
    x[0] = fmaf(u0.x, icnt, sb[cbase + 0]);
    x[1] = fmaf(u0.y, icnt, sb[cbase + 1]);
    x[2] = fmaf(u0.z, icnt, sb[cbase + 2]);
    x[3] = fmaf(u0.w, icnt, sb[cbase + 3]);
    x[4] = fmaf(u1.x, icnt, sb[cbase + 4]);
    x[5] = fmaf(u1.y, icnt, sb[cbase + 5]);
    x[6] = fmaf(u1.z, icnt, sb[cbase + 6]);
    x[7] = fmaf(u1.w, icnt, sb[cbase + 7]);

    float mu = 0.f;
    #pragma unroll
    for (int d = 0; d < 8; d++) mu += x[d];
    mu += __shfl_xor_sync(0xFFFFFFFFu, mu, 1);
    mu += __shfl_xor_sync(0xFFFFFFFFu, mu, 2);
    mu *= (1.0f / HIDDEN);

    float var = 0.f;
    #pragma unroll
    for (int d = 0; d < 8; d++) { const float dv = x[d] - mu; var += dv * dv; }
    var += __shfl_xor_sync(0xFFFFFFFFu, var, 1);
    var += __shfl_xor_sync(0xFFFFFFFFu, var, 2);
    var *= (1.0f / HIDDEN);
    const float rstd = rsqrtf(var + LN_EPS);

    float4 o0, o1;
    float y;
    y = (x[0] - mu) * rstd * sg[cbase + 0] + sbt[cbase + 0]; o0.x = y / (1.0f + __expf(-y));
    y = (x[1] - mu) * rstd * sg[cbase + 1] + sbt[cbase + 1]; o0.y = y / (1.0f + __expf(-y));
    y = (x[2] - mu) * rstd * sg[cbase + 2] + sbt[cbase + 2]; o0.z = y / (1.0f + __expf(-y));
    y = (x[3] - mu) * rstd * sg[cbase + 3] + sbt[cbase + 3]; o0.w = y / (1.0f + __expf(-y));
    y = (x[4] - mu) * rstd * sg[cbase + 4] + sbt[cbase + 4]; o1.x = y / (1.0f + __expf(-y));
    y = (x[5] - mu) * rstd * sg[cbase + 5] + sbt[cbase + 5]; o1.y = y / (1.0f + __expf(-y));
    y = (x[6] - mu) * rstd * sg[cbase + 6] + sbt[cbase + 6]; o1.z = y / (1.0f + __expf(-y));
    y = (x[7] - mu) * rstd * sg[cbase + 7] + sbt[cbase + 7]; o1.w = y / (1.0f + __expf(-y));

    float4* op = (float4*)&out[(size_t)n * 32 + cbase];
    op[0] = o0;
    op[1] = o1;
}

// ---------------------------------------------------------------------------
extern "C" void kernel_launch(void* const* d_in, const int* in_sizes, int n_in,
                              void* d_out, int out_size) {
    const float* positions = (const float*)d_in[0];
    const int*   edge_idx  = (const int*)d_in[1];    // int32
    const float* Wq   = (const float*)d_in[2];
    const float* bq   = (const float*)d_in[3];
    const float* Wk   = (const float*)d_in[4];
    const float* bk   = (const float*)d_in[5];
    const float* Wv   = (const float*)d_in[6];
    const float* bv   = (const float*)d_in[7];
    const float* Wout = (const float*)d_in[8];
    const float* bout = (const float*)d_in[9];
    const float* gamma = (const float*)d_in[10];
    const float* beta  = (const float*)d_in[11];
    float* out = (float*)d_out;

    const int zero_blocks = (N_NODES * 4 + 255) / 256;      // 1563
    init_kernel<<<zero_blocks + 1, 256>>>(Wq, bq, Wk, bk, Wv, bv, Wout);
    edge_kernel<<<(N_EDGES + 255) / 256, 256>>>(positions, edge_idx);
    node_kernel<<<(N_NODES * 4 + 255) / 256, 256>>>(bout, gamma, beta, out);
}